// round 8
// baseline (speedup 1.0000x reference)
#include <cuda_runtime.h>
#include <math.h>
#include <float.h>

// Problem constants (fixed by the dataset)
#define S_   7
#define B_   2
#define C_   80
#define NGT  32
#define BT_  8192
#define CELLF 90                    // B*5 + C
#define NCELLS (BT_ * S_ * S_)      // 401408
#define NBOX   (NCELLS * B_)        // 802816
#define NGTS   (BT_ * NGT)          // 262144

#define NTHR 128
#define NBLK (NGTS / NTHR)          // 2048 blocks -> exactly 1 GT per thread
#define NTOT (NBLK * NTHR)          // 262144
#define NWARP (NTHR / 32)           // 4

// Per-block partial sums: [coord, obj, posconf_sq, cls, npos, noobj_all]
__device__ double g_part[NBLK][6];
__device__ unsigned int g_count = 0;

__device__ __forceinline__ float sigmoidf_(float x) {
    return 1.0f / (1.0f + __expf(-x));
}

__global__ void __launch_bounds__(NTHR, 4)
yolo_loss_coop(const float* __restrict__ preds,
               const float* __restrict__ gt_boxes,
               const int* __restrict__ gt_labels,
               const unsigned char* __restrict__ gt_valid,
               float* __restrict__ out)
{
    __shared__ __align__(8) float scell[NTHR * CELLF];   // 46,080 B
    __shared__ double shred[NWARP][6];

    const int tid  = threadIdx.x;
    const int lane = tid & 31;
    const int wid  = tid >> 5;
    const int t    = blockIdx.x * NTHR + tid;      // GT index, exact
    const unsigned FULL = 0xffffffffu;

    float coord, obj, posconf, clsl, npos, noobj = 0.f;

    // ---- GT metadata (coalesced) ----
    const float mval = (__ldg(gt_valid + t) != 0) ? 1.0f : 0.0f;
    const float4 gb  = __ldg((const float4*)gt_boxes + t);
    const int   label = __ldg(gt_labels + t);

    const float x1 = gb.x, y1 = gb.y, x2 = gb.z, y2 = gb.w;
    const float cx = (x1 + x2) * 0.5f;
    const float cy = (y1 + y2) * 0.5f;
    const float w  = fmaxf(x2 - x1, 1e-6f);
    const float h  = fmaxf(y2 - y1, 1e-6f);
    const int gi = min(max((int)floorf(cx * (float)S_), 0), S_ - 1);
    const int gj = min(max((int)floorf(cy * (float)S_), 0), S_ - 1);

    const int b       = t >> 5;                    // t / NGT
    const int cellIdx = b * (S_ * S_) + gj * S_ + gi;

    // ================= Phase 2: conf over ALL cells (issued early) =================
    {
        const int c0 = t;
        const float* base0 = preds + (size_t)c0 * CELLF;
        const float v0a = __ldg(base0 + 4);
        const float v0b = __ldg(base0 + 9);
        float v1a = 0.f, v1b = 0.f;
        const int c1 = t + NTOT;
        const bool has2 = (c1 < NCELLS);
        if (has2) {
            const float* base1 = preds + (size_t)c1 * CELLF;
            v1a = __ldg(base1 + 4);
            v1b = __ldg(base1 + 9);
        }
        const float s0a = sigmoidf_(v0a), s0b = sigmoidf_(v0b);
        noobj = s0a * s0a + s0b * s0b;
        if (has2) {
            const float s1a = sigmoidf_(v1a), s1b = sigmoidf_(v1b);
            noobj += s1a * s1a + s1b * s1b;
        }
    }

    // ================= Cooperative warp gather: 32 cells -> smem =================
    // Each warp copies the cells of its own 32 GTs; lanes load consecutive float2s.
    {
        float2* sc2 = (float2*)(scell + wid * 32 * CELLF);   // this warp's 32 rows
        #pragma unroll 4
        for (int c = 0; c < 32; c++) {
            const int ci = __shfl_sync(FULL, cellIdx, c);
            const float2* src = (const float2*)(preds + (size_t)ci * CELLF);
            float2* dst = sc2 + c * (CELLF / 2);
            dst[lane] = __ldg(src + lane);                   // float2 0..31
            if (lane < 13)
                dst[32 + lane] = __ldg(src + 32 + lane);     // float2 32..44
        }
        __syncwarp();
    }

    // ================= Phase 1: one THREAD per GT, from smem =================
    {
        const float2* my = (const float2*)(scell) + tid * (CELLF / 2);

        // softmax over the 80 class logits: float2 slots 5..44
        float s0 = 0.f, s1 = 0.f, q0 = 0.f, q1 = 0.f;
        #pragma unroll
        for (int i = 5; i < 45; i++) {
            const float2 v = my[i];
            const float ea = __expf(v.x);
            const float eb = __expf(v.y);
            s0 += ea; q0 += ea * ea;
            s1 += eb; q1 += eb * eb;
        }
        const float s  = s0 + s1;
        const float sq = q0 + q1;
        const float el = __expf(scell[tid * CELLF + 10 + label]);
        const float inv = 1.0f / s;
        const float cls_term = sq * inv * inv - 2.0f * el * inv + 1.0f;

        // box floats 0..9 (float2 slots 0..4)
        float bx[10];
        #pragma unroll
        for (int j = 0; j < 5; j++) { bx[2*j] = my[j].x; bx[2*j+1] = my[j].y; }

        const float area_g = (x2 - x1) * (y2 - y1);
        float iou[2], sxk[2], syk[2], twk[2], thk[2], tok[2];
        #pragma unroll
        for (int k = 0; k < 2; k++) {
            const float tx = bx[k*5+0], ty = bx[k*5+1];
            const float tw = bx[k*5+2], th = bx[k*5+3];
            const float sx = sigmoidf_(tx);
            const float sy = sigmoidf_(ty);
            const float pw = tw * tw, ph = th * th;
            const float px = (sx + (float)gi) * (1.0f / S_);
            const float py = (sy + (float)gj) * (1.0f / S_);
            const float px1 = px - 0.5f * pw, px2v = px + 0.5f * pw;
            const float py1 = py - 0.5f * ph, py2v = py + 0.5f * ph;
            const float iw = fmaxf(0.f, fminf(px2v, x2) - fmaxf(px1, x1));
            const float ih = fmaxf(0.f, fminf(py2v, y2) - fmaxf(py1, y1));
            const float inter = iw * ih;
            iou[k] = inter / (pw * ph + area_g - inter + 1e-6f);
            sxk[k] = sx; syk[k] = sy; twk[k] = tw; thk[k] = th; tok[k] = bx[k*5+4];
        }
        const int   best = (iou[1] > iou[0]) ? 1 : 0;
        const float iou_best = fmaxf(iou[0], iou[1]);

        const float so  = sigmoidf_(tok[best]);
        const float tgx = cx * (float)S_ - (float)gi;
        const float tgy = cy * (float)S_ - (float)gj;
        const float tgw = sqrtf(w), tgh = sqrtf(h);
        const float dx = sxk[best] - tgx, dy = syk[best] - tgy;
        const float dw = twk[best] - tgw, dh = thk[best] - tgh;
        const float dob = so - iou_best;

        coord   = mval * (dx*dx + dy*dy + dw*dw + dh*dh);
        obj     = mval * dob * dob;
        posconf = mval * so * so;
        npos    = mval;
        clsl    = mval * cls_term;
    }

    // ================= Block reduction -> g_part =================
    float vals[6] = {coord, obj, posconf, clsl, npos, noobj};
    #pragma unroll
    for (int j = 0; j < 6; j++) {
        #pragma unroll
        for (int o = 16; o; o >>= 1)
            vals[j] += __shfl_xor_sync(FULL, vals[j], o);
    }
    if (lane == 0) {
        #pragma unroll
        for (int j = 0; j < 6; j++) shred[wid][j] = (double)vals[j];
    }
    __syncthreads();
    if (tid < 6) {
        double acc = 0.0;
        #pragma unroll
        for (int wI = 0; wI < NWARP; wI++) acc += shred[wI][tid];
        g_part[blockIdx.x][tid] = acc;
    }

    // ================= Grid-wide finalize: last block reduces =================
    __shared__ bool is_last;
    __threadfence();
    if (tid == 0) {
        const unsigned prev = atomicAdd(&g_count, 1u);
        is_last = (prev == (unsigned)(NBLK - 1));
        if (is_last) g_count = 0u;          // reset for next graph replay
    }
    __syncthreads();
    if (!is_last) return;

    double a[6] = {0, 0, 0, 0, 0, 0};
    for (int bb = tid; bb < NBLK; bb += NTHR) {
        #pragma unroll
        for (int j = 0; j < 6; j++) a[j] += __ldcg(&g_part[bb][j]);
    }
    #pragma unroll
    for (int j = 0; j < 6; j++) {
        #pragma unroll
        for (int o = 16; o; o >>= 1)
            a[j] += __shfl_xor_sync(FULL, a[j], o);
    }
    if (lane == 0) {
        #pragma unroll
        for (int j = 0; j < 6; j++) shred[wid][j] = a[j];
    }
    __syncthreads();
    if (tid == 0) {
        double tt[6];
        #pragma unroll
        for (int j = 0; j < 6; j++) {
            tt[j] = 0.0;
            for (int wI = 0; wI < NWARP; wI++) tt[j] += shred[wI][j];
        }
        const double nposd = fmax(tt[4], 1.0);
        const double nneg  = fmax((double)NBOX - tt[4], 1.0);
        const double ncell = fmax(tt[4], 1.0);   // GT cells are distinct per batch item
        const double loss = 5.0 * tt[0] / nposd          // LC * coord
                          + tt[1] / nposd                // obj
                          + 0.5 * (tt[5] - tt[2]) / nneg // LN * noobj (all - positive)
                          + tt[3] / ncell;               // cls
        *out = (float)loss;
    }
}

extern "C" void kernel_launch(void* const* d_in, const int* in_sizes, int n_in,
                              void* d_out, int out_size)
{
    const float*         preds     = (const float*)d_in[0];
    const float*         gt_boxes  = (const float*)d_in[1];
    const int*           gt_labels = (const int*)d_in[2];
    const unsigned char* gt_valid  = (const unsigned char*)d_in[3];
    float* out = (float*)d_out;

    yolo_loss_coop<<<NBLK, NTHR>>>(preds, gt_boxes, gt_labels, gt_valid, out);
}

// round 9
// speedup vs baseline: 1.3756x; 1.3756x over previous
#include <cuda_runtime.h>
#include <math.h>
#include <float.h>
#include <stdint.h>

// Problem constants (fixed by the dataset)
#define S_   7
#define B_   2
#define C_   80
#define NGT  32
#define BT_  8192
#define CELLF 90                    // B*5 + C
#define NCELLS (BT_ * S_ * S_)      // 401408
#define NBOX   (NCELLS * B_)        // 802816
#define NGTS   (BT_ * NGT)          // 262144

#define NTHR 128
#define NBLK (NGTS / NTHR)          // 2048 blocks -> exactly 1 GT per thread
#define NTOT (NBLK * NTHR)          // 262144
#define NWARP (NTHR / 32)           // 4

// Per-block partial sums: [coord, obj, posconf_sq, cls, npos, noobj_all]
__device__ double g_part[NBLK][6];
__device__ unsigned int g_count = 0;

__device__ __forceinline__ float sigmoidf_(float x) {
    return 1.0f / (1.0f + __expf(-x));
}

__device__ __forceinline__ uint32_t smem_u32(const void* p) {
    uint32_t a;
    asm("{ .reg .u64 t; cvta.to.shared.u64 t, %1; cvt.u32.u64 %0, t; }"
        : "=r"(a) : "l"(p));
    return a;
}

__device__ __forceinline__ void cp8(uint32_t dst, const void* src) {
    asm volatile("cp.async.ca.shared.global [%0], [%1], 8;"
                 :: "r"(dst), "l"(src) : "memory");
}

__global__ void __launch_bounds__(NTHR, 4)
yolo_loss_async(const float* __restrict__ preds,
                const float* __restrict__ gt_boxes,
                const int* __restrict__ gt_labels,
                const unsigned char* __restrict__ gt_valid,
                float* __restrict__ out)
{
    __shared__ __align__(8) float scell[NTHR * CELLF];   // 46,080 B
    __shared__ double shred[NWARP][6];

    const int tid  = threadIdx.x;
    const int lane = tid & 31;
    const int wid  = tid >> 5;
    const int t    = blockIdx.x * NTHR + tid;      // GT index, exact
    const unsigned FULL = 0xffffffffu;

    float coord, obj, posconf, clsl, npos, noobj = 0.f;

    // ---- GT metadata (coalesced) ----
    const float mval = (__ldg(gt_valid + t) != 0) ? 1.0f : 0.0f;
    const float4 gb  = __ldg((const float4*)gt_boxes + t);
    const int   label = __ldg(gt_labels + t);

    const float x1 = gb.x, y1 = gb.y, x2 = gb.z, y2 = gb.w;
    const float cx = (x1 + x2) * 0.5f;
    const float cy = (y1 + y2) * 0.5f;
    const float w  = fmaxf(x2 - x1, 1e-6f);
    const float h  = fmaxf(y2 - y1, 1e-6f);
    const int gi = min(max((int)floorf(cx * (float)S_), 0), S_ - 1);
    const int gj = min(max((int)floorf(cy * (float)S_), 0), S_ - 1);

    const int b       = t >> 5;                    // t / NGT
    const int cellIdx = b * (S_ * S_) + gj * S_ + gi;

    // ---- Phase 2 conf loads issued EARLY (overlap the async gather) ----
    const float v0a = __ldg(preds + (size_t)t * CELLF + 4);
    const float v0b = __ldg(preds + (size_t)t * CELLF + 9);
    const int   c1   = t + NTOT;
    const bool  has2 = (c1 < NCELLS);
    float v1a = 0.f, v1b = 0.f;
    if (has2) {
        v1a = __ldg(preds + (size_t)c1 * CELLF + 4);
        v1b = __ldg(preds + (size_t)c1 * CELLF + 9);
    }

    // ================= Cooperative async gather: 32 cells/warp -> smem =================
    {
        const uint32_t sbase = smem_u32(scell) + (uint32_t)(wid * 32 * CELLF) * 4u;
        #pragma unroll 8
        for (int c = 0; c < 32; c++) {
            const int ci = __shfl_sync(FULL, cellIdx, c);
            const char* src = (const char*)(preds + (size_t)ci * CELLF);
            const uint32_t dst = sbase + (uint32_t)(c * CELLF) * 4u;
            cp8(dst + lane * 8, src + lane * 8);                     // float2 0..31
            if (lane < 13)
                cp8(dst + 256 + lane * 8, src + 256 + lane * 8);     // float2 32..44
        }
        asm volatile("cp.async.commit_group;" ::: "memory");
        asm volatile("cp.async.wait_group 0;" ::: "memory");
        __syncwarp();
    }

    // phase-2 math (loads arrived by now)
    {
        const float s0a = sigmoidf_(v0a), s0b = sigmoidf_(v0b);
        noobj = s0a * s0a + s0b * s0b;
        if (has2) {
            const float s1a = sigmoidf_(v1a), s1b = sigmoidf_(v1b);
            noobj += s1a * s1a + s1b * s1b;
        }
    }

    // ================= Phase 1: one THREAD per GT, from smem =================
    {
        const float2* my = (const float2*)(scell) + tid * (CELLF / 2);

        // softmax over the 80 class logits: float2 slots 5..44
        float s0 = 0.f, s1 = 0.f, q0 = 0.f, q1 = 0.f;
        #pragma unroll
        for (int i = 5; i < 45; i++) {
            const float2 v = my[i];
            const float ea = __expf(v.x);
            const float eb = __expf(v.y);
            s0 += ea; q0 += ea * ea;
            s1 += eb; q1 += eb * eb;
        }
        const float s  = s0 + s1;
        const float sq = q0 + q1;
        const float el = __expf(scell[tid * CELLF + 10 + label]);
        const float inv = 1.0f / s;
        const float cls_term = sq * inv * inv - 2.0f * el * inv + 1.0f;

        // box floats 0..9 (float2 slots 0..4)
        float bx[10];
        #pragma unroll
        for (int j = 0; j < 5; j++) { bx[2*j] = my[j].x; bx[2*j+1] = my[j].y; }

        const float area_g = (x2 - x1) * (y2 - y1);
        float iou[2], sxk[2], syk[2], twk[2], thk[2], tok[2];
        #pragma unroll
        for (int k = 0; k < 2; k++) {
            const float tx = bx[k*5+0], ty = bx[k*5+1];
            const float tw = bx[k*5+2], th = bx[k*5+3];
            const float sx = sigmoidf_(tx);
            const float sy = sigmoidf_(ty);
            const float pw = tw * tw, ph = th * th;
            const float px = (sx + (float)gi) * (1.0f / S_);
            const float py = (sy + (float)gj) * (1.0f / S_);
            const float px1 = px - 0.5f * pw, px2v = px + 0.5f * pw;
            const float py1 = py - 0.5f * ph, py2v = py + 0.5f * ph;
            const float iw = fmaxf(0.f, fminf(px2v, x2) - fmaxf(px1, x1));
            const float ih = fmaxf(0.f, fminf(py2v, y2) - fmaxf(py1, y1));
            const float inter = iw * ih;
            iou[k] = inter / (pw * ph + area_g - inter + 1e-6f);
            sxk[k] = sx; syk[k] = sy; twk[k] = tw; thk[k] = th; tok[k] = bx[k*5+4];
        }
        const int   best = (iou[1] > iou[0]) ? 1 : 0;
        const float iou_best = fmaxf(iou[0], iou[1]);

        const float so  = sigmoidf_(tok[best]);
        const float tgx = cx * (float)S_ - (float)gi;
        const float tgy = cy * (float)S_ - (float)gj;
        const float tgw = sqrtf(w), tgh = sqrtf(h);
        const float dx = sxk[best] - tgx, dy = syk[best] - tgy;
        const float dw = twk[best] - tgw, dh = thk[best] - tgh;
        const float dob = so - iou_best;

        coord   = mval * (dx*dx + dy*dy + dw*dw + dh*dh);
        obj     = mval * dob * dob;
        posconf = mval * so * so;
        npos    = mval;
        clsl    = mval * cls_term;
    }

    // ================= Block reduction -> g_part =================
    float vals[6] = {coord, obj, posconf, clsl, npos, noobj};
    #pragma unroll
    for (int j = 0; j < 6; j++) {
        #pragma unroll
        for (int o = 16; o; o >>= 1)
            vals[j] += __shfl_xor_sync(FULL, vals[j], o);
    }
    if (lane == 0) {
        #pragma unroll
        for (int j = 0; j < 6; j++) shred[wid][j] = (double)vals[j];
    }
    __syncthreads();
    if (tid < 6) {
        double acc = 0.0;
        #pragma unroll
        for (int wI = 0; wI < NWARP; wI++) acc += shred[wI][tid];
        g_part[blockIdx.x][tid] = acc;
    }

    // ================= Grid-wide finalize: last block reduces =================
    __shared__ bool is_last;
    __threadfence();
    if (tid == 0) {
        const unsigned prev = atomicAdd(&g_count, 1u);
        is_last = (prev == (unsigned)(NBLK - 1));
        if (is_last) g_count = 0u;          // reset for next graph replay
    }
    __syncthreads();
    if (!is_last) return;

    double a[6] = {0, 0, 0, 0, 0, 0};
    for (int bb = tid; bb < NBLK; bb += NTHR) {
        #pragma unroll
        for (int j = 0; j < 6; j++) a[j] += __ldcg(&g_part[bb][j]);
    }
    #pragma unroll
    for (int j = 0; j < 6; j++) {
        #pragma unroll
        for (int o = 16; o; o >>= 1)
            a[j] += __shfl_xor_sync(FULL, a[j], o);
    }
    if (lane == 0) {
        #pragma unroll
        for (int j = 0; j < 6; j++) shred[wid][j] = a[j];
    }
    __syncthreads();
    if (tid == 0) {
        double tt[6];
        #pragma unroll
        for (int j = 0; j < 6; j++) {
            tt[j] = 0.0;
            for (int wI = 0; wI < NWARP; wI++) tt[j] += shred[wI][j];
        }
        const double nposd = fmax(tt[4], 1.0);
        const double nneg  = fmax((double)NBOX - tt[4], 1.0);
        const double ncell = fmax(tt[4], 1.0);   // GT cells are distinct per batch item
        const double loss = 5.0 * tt[0] / nposd          // LC * coord
                          + tt[1] / nposd                // obj
                          + 0.5 * (tt[5] - tt[2]) / nneg // LN * noobj (all - positive)
                          + tt[3] / ncell;               // cls
        *out = (float)loss;
    }
}

extern "C" void kernel_launch(void* const* d_in, const int* in_sizes, int n_in,
                              void* d_out, int out_size)
{
    const float*         preds     = (const float*)d_in[0];
    const float*         gt_boxes  = (const float*)d_in[1];
    const int*           gt_labels = (const int*)d_in[2];
    const unsigned char* gt_valid  = (const unsigned char*)d_in[3];
    float* out = (float*)d_out;

    yolo_loss_async<<<NBLK, NTHR>>>(preds, gt_boxes, gt_labels, gt_valid, out);
}

// round 10
// speedup vs baseline: 1.8279x; 1.3288x over previous
#include <cuda_runtime.h>
#include <math.h>
#include <float.h>

// Problem constants (fixed by the dataset)
#define S_   7
#define B_   2
#define C_   80
#define NGT  32
#define BT_  8192
#define CELLF 90                    // B*5 + C
#define NCELLS (BT_ * S_ * S_)      // 401408
#define NBOX   (NCELLS * B_)        // 802816
#define NGTS   (BT_ * NGT)          // 262144

#define NTHR 128
#define NBLK 1024                   // fine-grained balance; 2 GTs per thread
#define NTOT (NBLK * NTHR)          // 131072 threads
#define GPT  (NGTS / NTOT)          // 2
#define NWARP (NTHR / 32)           // 4

// Per-block partial sums: [coord, obj, posconf_sq, cls, npos, noobj_all]
__device__ double g_part[NBLK][6];
__device__ unsigned int g_count = 0;

__device__ __forceinline__ float sigmoidf_(float x) {
    return 1.0f / (1.0f + __expf(-x));
}

__global__ void __launch_bounds__(NTHR, 8)
yolo_loss_fused(const float* __restrict__ preds,
                const float* __restrict__ gt_boxes,
                const int* __restrict__ gt_labels,
                const unsigned char* __restrict__ gt_valid,
                float* __restrict__ out)
{
    const int tid  = threadIdx.x;
    const int lane = tid & 31;
    const int wid  = tid >> 5;
    const int t0   = blockIdx.x * NTHR + tid;
    const unsigned FULL = 0xffffffffu;

    float coord = 0.f, obj = 0.f, posconf = 0.f, clsl = 0.f, npos = 0.f, noobj = 0.f;

    // ===== Phase 2 conf loads hoisted: independent MLP during gather latency =====
    // cells c = t0 + k*NTOT, k=0..2 always valid; k=3 valid iff t0 < 8192
    {
        const float a0 = __ldg(preds + (size_t)t0 * CELLF + 4);
        const float b0 = __ldg(preds + (size_t)t0 * CELLF + 9);
        const float a1 = __ldg(preds + (size_t)(t0 + NTOT) * CELLF + 4);
        const float b1 = __ldg(preds + (size_t)(t0 + NTOT) * CELLF + 9);
        const float a2 = __ldg(preds + (size_t)(t0 + 2 * NTOT) * CELLF + 4);
        const float b2 = __ldg(preds + (size_t)(t0 + 2 * NTOT) * CELLF + 9);
        float a3 = 0.f, b3 = 0.f;
        const bool has4 = (t0 + 3 * NTOT) < NCELLS;
        if (has4) {
            a3 = __ldg(preds + (size_t)(t0 + 3 * NTOT) * CELLF + 4);
            b3 = __ldg(preds + (size_t)(t0 + 3 * NTOT) * CELLF + 9);
        }
        const float s0 = sigmoidf_(a0), s1 = sigmoidf_(b0);
        const float s2 = sigmoidf_(a1), s3 = sigmoidf_(b1);
        const float s4 = sigmoidf_(a2), s5 = sigmoidf_(b2);
        noobj = s0*s0 + s1*s1 + s2*s2 + s3*s3 + s4*s4 + s5*s5;
        if (has4) {
            const float s6 = sigmoidf_(a3), s7 = sigmoidf_(b3);
            noobj += s6*s6 + s7*s7;
        }
    }

    // ================= Phase 1: 2 GTs per thread, fully unrolled =================
    #pragma unroll
    for (int g = 0; g < GPT; g++) {
        const int t = t0 + g * NTOT;

        const float mval = (__ldg(gt_valid + t) != 0) ? 1.0f : 0.0f;
        const float4 gb  = __ldg((const float4*)gt_boxes + t);
        const int   label = __ldg(gt_labels + t);

        const float x1 = gb.x, y1 = gb.y, x2 = gb.z, y2 = gb.w;
        const float cx = (x1 + x2) * 0.5f;
        const float cy = (y1 + y2) * 0.5f;
        const float w  = fmaxf(x2 - x1, 1e-6f);
        const float h  = fmaxf(y2 - y1, 1e-6f);
        const int gi = min(max((int)floorf(cx * (float)S_), 0), S_ - 1);
        const int gj = min(max((int)floorf(cy * (float)S_), 0), S_ - 1);

        const int  b       = t >> 5;                       // t / NGT
        const int  cellIdx = b * (S_ * S_) + gj * S_ + gi;
        const float* cell  = preds + (size_t)cellIdx * CELLF;

        // label-logit gather (independent scalar load, overlaps everything)
        const float cl = __ldg(cell + 10 + label);

        // 16B-aligned vec4 view: off = 0 (even cell) or 2 floats (odd cell)
        const int   off  = (cellIdx & 1) << 1;             // 0 or 2
        const float msh  = (float)(off >> 1);              // 1.0 if shifted
        const float mns  = 1.0f - msh;                     // 1.0 if not shifted
        const float4* v4 = (const float4*)(cell - off);

        // ---- head: loaded positions 0..11 ----
        float p[12];
        {
            const float4 a  = __ldg(v4 + 0);
            const float4 bq = __ldg(v4 + 1);
            const float4 c  = __ldg(v4 + 2);
            p[0]=a.x;  p[1]=a.y;  p[2]=a.z;  p[3]=a.w;
            p[4]=bq.x; p[5]=bq.y; p[6]=bq.z; p[7]=bq.w;
            p[8]=c.x;  p[9]=c.y;  p[10]=c.z; p[11]=c.w;
        }
        float bx[10];
        #pragma unroll
        for (int j = 0; j < 10; j++) bx[j] = (off != 0) ? p[j + 2] : p[j];

        // off=0: positions 10,11 are class logits 10,11 (else box floats)
        const float e10 = __expf(p[10]);
        const float e11 = __expf(p[11]);
        float s0 = mns * (e10 + e11),          s1 = 0.f, s2 = 0.f, s3 = 0.f;
        float q0 = mns * (e10*e10 + e11*e11),  q1 = 0.f, q2 = 0.f, q3 = 0.f;

        // ---- body: positions 12..91 (vec 3..22) in 4 chunks of 5 vec4 ----
        #pragma unroll
        for (int ch = 0; ch < 4; ch++) {
            float4 u0 = __ldg(v4 + 3 + ch*5 + 0);
            float4 u1 = __ldg(v4 + 3 + ch*5 + 1);
            float4 u2 = __ldg(v4 + 3 + ch*5 + 2);
            float4 u3 = __ldg(v4 + 3 + ch*5 + 3);
            float4 u4 = __ldg(v4 + 3 + ch*5 + 4);
            float q[20] = {u0.x,u0.y,u0.z,u0.w, u1.x,u1.y,u1.z,u1.w,
                           u2.x,u2.y,u2.z,u2.w, u3.x,u3.y,u3.z,u3.w,
                           u4.x,u4.y,u4.z,u4.w};
            #pragma unroll
            for (int i = 0; i < 20; i++) {
                float e = __expf(q[i]);
                if (ch == 3 && i >= 18) e *= msh;   // 90,91 valid only when off=2
                if      ((i & 3) == 0) { s0 += e; q0 += e*e; }
                else if ((i & 3) == 1) { s1 += e; q1 += e*e; }
                else if ((i & 3) == 2) { s2 += e; q2 += e*e; }
                else                   { s3 += e; q3 += e*e; }
            }
        }
        const float s  = (s0 + s1) + (s2 + s3);
        const float sq = (q0 + q1) + (q2 + q3);
        const float el = __expf(cl);
        const float inv = 1.0f / s;
        const float cls_term = sq * inv * inv - 2.0f * el * inv + 1.0f;

        // ---- IoU over both candidate boxes ----
        const float area_g = (x2 - x1) * (y2 - y1);
        float iou[2], sxk[2], syk[2], twk[2], thk[2], tok[2];
        #pragma unroll
        for (int k = 0; k < 2; k++) {
            const float tx = bx[k*5+0], ty = bx[k*5+1];
            const float tw = bx[k*5+2], th = bx[k*5+3];
            const float sx = sigmoidf_(tx);
            const float sy = sigmoidf_(ty);
            const float pw = tw * tw, ph = th * th;
            const float px = (sx + (float)gi) * (1.0f / S_);
            const float py = (sy + (float)gj) * (1.0f / S_);
            const float px1 = px - 0.5f * pw, px2v = px + 0.5f * pw;
            const float py1 = py - 0.5f * ph, py2v = py + 0.5f * ph;
            const float iw = fmaxf(0.f, fminf(px2v, x2) - fmaxf(px1, x1));
            const float ih = fmaxf(0.f, fminf(py2v, y2) - fmaxf(py1, y1));
            const float inter = iw * ih;
            iou[k] = inter / (pw * ph + area_g - inter + 1e-6f);
            sxk[k] = sx; syk[k] = sy; twk[k] = tw; thk[k] = th; tok[k] = bx[k*5+4];
        }
        const int   best = (iou[1] > iou[0]) ? 1 : 0;
        const float iou_best = fmaxf(iou[0], iou[1]);

        const float so  = sigmoidf_(tok[best]);
        const float tgx = cx * (float)S_ - (float)gi;
        const float tgy = cy * (float)S_ - (float)gj;
        const float tgw = sqrtf(w), tgh = sqrtf(h);
        const float dx = sxk[best] - tgx, dy = syk[best] - tgy;
        const float dw = twk[best] - tgw, dh = thk[best] - tgh;
        const float dob = so - iou_best;

        coord   += mval * (dx*dx + dy*dy + dw*dw + dh*dh);
        obj     += mval * dob * dob;
        posconf += mval * so * so;
        npos    += mval;
        clsl    += mval * cls_term;
    }

    // ================= Block reduction -> g_part =================
    float vals[6] = {coord, obj, posconf, clsl, npos, noobj};
    #pragma unroll
    for (int j = 0; j < 6; j++) {
        #pragma unroll
        for (int o = 16; o; o >>= 1)
            vals[j] += __shfl_xor_sync(FULL, vals[j], o);
    }
    __shared__ double sh[NWARP][6];
    if (lane == 0) {
        #pragma unroll
        for (int j = 0; j < 6; j++) sh[wid][j] = (double)vals[j];
    }
    __syncthreads();
    if (tid < 6) {
        double acc = 0.0;
        #pragma unroll
        for (int wI = 0; wI < NWARP; wI++) acc += sh[wI][tid];
        g_part[blockIdx.x][tid] = acc;
    }

    // ================= Grid-wide finalize: last block reduces =================
    __shared__ bool is_last;
    __threadfence();
    if (tid == 0) {
        const unsigned prev = atomicAdd(&g_count, 1u);
        is_last = (prev == (unsigned)(NBLK - 1));
        if (is_last) g_count = 0u;          // reset for next graph replay
    }
    __syncthreads();
    if (!is_last) return;

    double a[6] = {0, 0, 0, 0, 0, 0};
    for (int bb = tid; bb < NBLK; bb += NTHR) {
        #pragma unroll
        for (int j = 0; j < 6; j++) a[j] += __ldcg(&g_part[bb][j]);
    }
    #pragma unroll
    for (int j = 0; j < 6; j++) {
        #pragma unroll
        for (int o = 16; o; o >>= 1)
            a[j] += __shfl_xor_sync(FULL, a[j], o);
    }
    __shared__ double shf[NWARP][6];
    if (lane == 0) {
        #pragma unroll
        for (int j = 0; j < 6; j++) shf[wid][j] = a[j];
    }
    __syncthreads();
    if (tid == 0) {
        double tt[6];
        #pragma unroll
        for (int j = 0; j < 6; j++) {
            tt[j] = 0.0;
            for (int wI = 0; wI < NWARP; wI++) tt[j] += shf[wI][j];
        }
        const double nposd = fmax(tt[4], 1.0);
        const double nneg  = fmax((double)NBOX - tt[4], 1.0);
        const double ncell = fmax(tt[4], 1.0);   // GT cells are distinct per batch item
        const double loss = 5.0 * tt[0] / nposd          // LC * coord
                          + tt[1] / nposd                // obj
                          + 0.5 * (tt[5] - tt[2]) / nneg // LN * noobj (all - positive)
                          + tt[3] / ncell;               // cls
        *out = (float)loss;
    }
}

extern "C" void kernel_launch(void* const* d_in, const int* in_sizes, int n_in,
                              void* d_out, int out_size)
{
    const float*         preds     = (const float*)d_in[0];
    const float*         gt_boxes  = (const float*)d_in[1];
    const int*           gt_labels = (const int*)d_in[2];
    const unsigned char* gt_valid  = (const unsigned char*)d_in[3];
    float* out = (float*)d_out;

    yolo_loss_fused<<<NBLK, NTHR>>>(preds, gt_boxes, gt_labels, gt_valid, out);
}